// round 17
// baseline (speedup 1.0000x reference)
#include <cuda_runtime.h>
#include <cuda_fp16.h>

// out[v,:] = coef * sum_k u_k * (2*x[v] + u_k),  u_k = x[nbr[v,k]]
// N=100000, K=16, D=128, coef = (2/6)/16 = 1/48.
// Main kernel: fp16 gather, 1 node/warp, single accumulator, single flush
// (R16 winner, byte-identical here).
// R17 delta: convert pass restructured — each thread converts 64B of x via
// 4 independent __ldcs float4 loads (MLP=4) + 2 uint4 STG.128 stores.

#define TMP_N 100000
#define TMP_D 128
#define TMP_K 16

// fp16 copy of x: [N, 32] uint2 (4 halves per lane); also viewed as uint4.
__device__ __align__(16) uint2 g_xh[TMP_N * TMP_D / 4];

__global__ __launch_bounds__(256) void TMP_convert_kernel(
    const float4* __restrict__ x, int n16)   // n16 = N*D/16 (64B chunks)
{
    int i = blockIdx.x * blockDim.x + threadIdx.x;
    if (i >= n16) return;

    // 4 independent evict-first loads (64B contiguous).
    const float4* src = x + 4 * i;
    float4 v0 = __ldcs(&src[0]);
    float4 v1 = __ldcs(&src[1]);
    float4 v2 = __ldcs(&src[2]);
    float4 v3 = __ldcs(&src[3]);

    __half2 h;
    uint4 p0, p1;
    h = __floats2half2_rn(v0.x, v0.y); p0.x = *reinterpret_cast<unsigned int*>(&h);
    h = __floats2half2_rn(v0.z, v0.w); p0.y = *reinterpret_cast<unsigned int*>(&h);
    h = __floats2half2_rn(v1.x, v1.y); p0.z = *reinterpret_cast<unsigned int*>(&h);
    h = __floats2half2_rn(v1.z, v1.w); p0.w = *reinterpret_cast<unsigned int*>(&h);
    h = __floats2half2_rn(v2.x, v2.y); p1.x = *reinterpret_cast<unsigned int*>(&h);
    h = __floats2half2_rn(v2.z, v2.w); p1.y = *reinterpret_cast<unsigned int*>(&h);
    h = __floats2half2_rn(v3.x, v3.y); p1.z = *reinterpret_cast<unsigned int*>(&h);
    h = __floats2half2_rn(v3.z, v3.w); p1.w = *reinterpret_cast<unsigned int*>(&h);

    uint4* dst = reinterpret_cast<uint4*>(g_xh) + 2 * i;
    dst[0] = p0;
    dst[1] = p1;
}

static __device__ __forceinline__ __half2 h2bits(unsigned int u) {
    return *reinterpret_cast<__half2*>(&u);
}

__global__ __launch_bounds__(256) void TMessagePassing_11974368821731_kernel(
    const int4* __restrict__ nbr4,   // [N, 4] int4 (= [N,16] int)
    float4*     __restrict__ out,    // [N, 32] float4
    int n)
{
    int warp = (int)((blockIdx.x * blockDim.x + threadIdx.x) >> 5);
    int lane = threadIdx.x & 31;
    if (warp >= n) return;

    const float coef = 1.0f / 48.0f;
    const uint2* __restrict__ xh = g_xh;

    // 16 neighbor indices via 4 vector loads (uniform -> broadcast).
    const int4* nv = nbr4 + (long long)warp * 4;
    int idx[TMP_K];
#pragma unroll
    for (int r = 0; r < 4; r++) {
        int4 q = __ldg(&nv[r]);
        idx[4 * r + 0] = q.x; idx[4 * r + 1] = q.y;
        idx[4 * r + 2] = q.z; idx[4 * r + 3] = q.w;
    }

    // Self row (fp16, L2-resident); w = 2*xv (exact: exponent bump).
    uint2 ps = __ldg(&xh[(unsigned)warp * 32u + (unsigned)lane]);
    __half2 w0 = __hadd2(h2bits(ps.x), h2bits(ps.x));
    __half2 w1 = __hadd2(h2bits(ps.y), h2bits(ps.y));

    // Single run of 16; per row: s = w + u; a += u*s (half2). One fp32 flush.
    __half2 a0, a1;
    {
        uint2 p = __ldg(&xh[(unsigned)idx[0] * 32u + (unsigned)lane]);
        __half2 u0 = h2bits(p.x), u1 = h2bits(p.y);
        a0 = __hmul2(u0, __hadd2(w0, u0));
        a1 = __hmul2(u1, __hadd2(w1, u1));
    }
#pragma unroll
    for (int j = 1; j < TMP_K; j++) {
        uint2 p = __ldg(&xh[(unsigned)idx[j] * 32u + (unsigned)lane]);
        __half2 u0 = h2bits(p.x), u1 = h2bits(p.y);
        a0 = __hfma2(u0, __hadd2(w0, u0), a0);
        a1 = __hfma2(u1, __hadd2(w1, u1), a1);
    }

    float2 f0 = __half22float2(a0);
    float2 f1 = __half22float2(a1);

    float4 o;
    o.x = coef * f0.x;
    o.y = coef * f0.y;
    o.z = coef * f1.x;
    o.w = coef * f1.y;

    // Streaming store: keep out from evicting xh in L2.
    __stcs(&out[(long long)warp * 32 + lane], o);
}

extern "C" void kernel_launch(void* const* d_in, const int* in_sizes, int n_in,
                              void* d_out, int out_size)
{
    const float4* x    = (const float4*)d_in[0];
    const int4*   nbr4 = (const int4*)d_in[1];
    float4*       out  = (float4*)d_out;

    int n   = in_sizes[1] / TMP_K;     // N nodes
    int n16 = in_sizes[0] / 16;        // 64B chunks of x (N*D = 12.8M, divisible)

    TMP_convert_kernel<<<(n16 + 255) / 256, 256>>>(x, n16);

    int warps_per_block = 256 / 32;    // 8 nodes per block
    int blocks = (n + warps_per_block - 1) / warps_per_block;
    TMessagePassing_11974368821731_kernel<<<blocks, 256>>>(nbr4, out, n);
}